// round 15
// baseline (speedup 1.0000x reference)
#include <cuda_runtime.h>
#include <math.h>
#include <stdint.h>

#define NTASK 16
#define NEMB  25
#define DIM   512
#define HID   1024
#define NTRIP 2000
#define NCPT  64
#define M_ALL (NTASK*NEMB)   // 400
#define GCOLS (3*HID)        // 3072
#define NBLK  128            // one wave -> grid barrier safe
#define NTHR  768            // 24 warps

// ---------------- scratch ----------------
__device__ float    g_G[M_ALL*GCOLS];
__device__ unsigned g_trip[NTASK*NTRIP];
__device__ int      g_cnt[NTASK];
__device__ float    g_q[NTASK*HID];
__device__ float    g_pooled[NTASK*DIM];
__device__ float    g_t1[NTASK*HID];
__device__ float    g_t2[NTASK*DIM];
__device__ unsigned g_bcnt[5];
__device__ unsigned g_bgen[5];

__device__ __forceinline__ float warp_sum(float v) {
    #pragma unroll
    for (int o = 16; o > 0; o >>= 1) v += __shfl_xor_sync(0xffffffffu, v, o);
    return v;
}

__device__ __forceinline__ uint32_t s2u(const void* p) {
    return (uint32_t)__cvta_generic_to_shared(p);
}

__device__ __forceinline__ void cpa16(uint32_t dst, const float* src) {
    asm volatile("cp.async.ca.shared.global [%0], [%1], 16;" :: "r"(dst), "l"(src));
}

__device__ __forceinline__ void grid_barrier(int s, unsigned nb) {
    __syncthreads();
    if (threadIdx.x == 0) {
        unsigned g0 = *((volatile unsigned*)&g_bgen[s]);
        __threadfence();
        unsigned old = atomicAdd(&g_bcnt[s], 1u);
        if (old == nb - 1u) {
            g_bcnt[s] = 0u;
            __threadfence();
            atomicAdd(&g_bgen[s], 1u);
        } else {
            while (*((volatile unsigned*)&g_bgen[s]) == g0) { }
            __threadfence();
        }
    }
    __syncthreads();
}

__device__ __forceinline__ void head_prefetch(const float* __restrict__ W,
                                              int Nout, int jb, int kb, int tid,
                                              float* wv) {
    if (tid < 512) {
        int j  = jb*64 + (tid & 63);
        int kh = tid >> 6;
        #pragma unroll
        for (int ii = 0; ii < 8; ii++)
            wv[ii] = __ldg(&W[(size_t)(kb*64 + kh*8 + ii)*Nout + j]);
    }
}

__device__ __forceinline__ void head_compute(const float* __restrict__ in,
                                             const float* __restrict__ bvec,
                                             const int* __restrict__ cntp,
                                             float* __restrict__ outp,
                                             int Nin, int Nout, int mode,
                                             int jb, int kb,
                                             float (*sf)[16], int tid,
                                             const float* wv) {
    int kb64 = kb * 64;
    for (int idx = tid; idx < 1024; idx += NTHR) {
        int il = idx >> 4, t = idx & 15;
        float v = in[t*Nin + kb64 + il];
        if (mode == 1)      v += (float)cntp[t] * bvec[kb64 + il];
        else if (mode == 2) v  = fmaxf(v + bvec[kb64 + il], 0.f);
        sf[il][t] = v;
    }
    __syncthreads();
    if (tid < 512) {
        int j  = jb*64 + (tid & 63);
        int kh = tid >> 6;
        float acc[16];
        #pragma unroll
        for (int t = 0; t < 16; t++) acc[t] = 0.f;
        const float4* sf4 = reinterpret_cast<const float4*>(sf);
        #pragma unroll
        for (int ii = 0; ii < 8; ii++) {
            int i = (kh << 3) + ii;
            float w = wv[ii];
            float4 f0 = sf4[i*4 + 0];
            float4 f1 = sf4[i*4 + 1];
            float4 f2 = sf4[i*4 + 2];
            float4 f3 = sf4[i*4 + 3];
            acc[0]  += f0.x*w; acc[1]  += f0.y*w; acc[2]  += f0.z*w; acc[3]  += f0.w*w;
            acc[4]  += f1.x*w; acc[5]  += f1.y*w; acc[6]  += f1.z*w; acc[7]  += f1.w*w;
            acc[8]  += f2.x*w; acc[9]  += f2.y*w; acc[10] += f2.z*w; acc[11] += f2.w*w;
            acc[12] += f3.x*w; acc[13] += f3.y*w; acc[14] += f3.z*w; acc[15] += f3.w*w;
        }
        #pragma unroll
        for (int t = 0; t < 16; t++)
            atomicAdd(&outp[t*Nout + j], acc[t]);
    }
}

// ============================================================================
// ONE persistent kernel: [gemm | mining] -> pool -> h1 -> h2 -> h3 -> final
// 768 threads: GEMM = 16 compute warps (32x24 tiles) + all threads load
// ============================================================================
__global__ __launch_bounds__(NTHR) void omega_kernel(const float* __restrict__ X,
                                                     const float* __restrict__ W1,
                                                     const float* __restrict__ b1,
                                                     const float* __restrict__ W2,
                                                     const float* __restrict__ b2,
                                                     const float* __restrict__ W3,
                                                     const float* __restrict__ b3,
                                                     const float* __restrict__ W4,
                                                     const float* __restrict__ b4v,
                                                     const float* __restrict__ Wc,
                                                     const float* __restrict__ bc,
                                                     float* __restrict__ G,
                                                     unsigned* __restrict__ trip,
                                                     int* __restrict__ cnt,
                                                     float* __restrict__ q,
                                                     float* __restrict__ pooled,
                                                     float* __restrict__ t1,
                                                     float* __restrict__ t2,
                                                     float* __restrict__ out) {
    extern __shared__ char dsm[];
    float*    xs   = reinterpret_cast<float*>(dsm);                      // mining
    float4 (*sG)[32]   = reinterpret_cast<float4(*)[32]>(dsm);          // pool
    char* rbm = dsm + 75*32*16;                                          // +38400
    float4 (*red)[32]  = reinterpret_cast<float4(*)[32]>(rbm);          // 24*32*16 = 12288
    float  (*sf)[16]   = reinterpret_cast<float(*)[16]>(rbm);           // 4096
    float  (*fred)[64] = reinterpret_cast<float(*)[64]>(rbm);           // 2048
    float*  sc         = reinterpret_cast<float*>(rbm + 8*64*4);
    unsigned* strip    = reinterpret_cast<unsigned*>(rbm + 12288);      // 8000

    // GEMM pipeline buffers (3-stage cp.async), conflict-free padded
    __shared__ __align__(16) float As[3][64][20];    // 15360 B
    __shared__ __align__(16) float Bs[3][16][200];   // 38400 B

    int bid = blockIdx.x;
    int tid = threadIdx.x;
    unsigned nb = gridDim.x;

    // ---- zero atomic accumulators ----
    {
        int gidx = bid*NTHR + tid;
        if (gidx < NTASK*DIM)  pooled[gidx] = 0.f;
        if (gidx < NTASK*HID)  t1[gidx]     = 0.f;
        if (gidx < NTASK*DIM)  t2[gidx]     = 0.f;
    }

    // ============================ stage A ============================
    if (bid < 112) {
        // GEMM: BM=64, BN=192, BK=16; warps 0-15 compute 32x24 tiles (2x8 grid)
        int m0 = (bid >> 4) * 64;
        int n0 = (bid & 15) * 192;
        int w = tid >> 5, lane = tid & 31;
        int wm = w & 1, wn = w >> 1;           // wn 0..11, compute only wn<8
        int grp = lane >> 2, tid4 = lane & 3;
        bool computer = (w < 16);

        float c[2][3][4];
        #pragma unroll
        for (int mt = 0; mt < 2; mt++)
            #pragma unroll
            for (int nt = 0; nt < 3; nt++)
                #pragma unroll
                for (int r = 0; r < 4; r++) c[mt][nt][r] = 0.f;

        // ---- loaders: B = 768 chunks (all threads), A = 256 chunks (tid>=512)
        int brow1 = tid / 48, bcol1 = (tid - brow1*48) * 4;
        int gc1 = n0 + bcol1;
        const float* bsrc1 = W1 + ((size_t)(((gc1 >> 10) << 9)) + brow1) * 1024 + (gc1 & 1023);
        uint32_t bdst1 = s2u(&Bs[0][brow1][bcol1]);

        int ac = tid - 512;
        int am = (ac >> 2) & 63, ak = (ac & 3) << 2;
        int gm = m0 + am; if (gm >= M_ALL) gm = M_ALL - 1;
        const float* asrc = X + (size_t)gm * DIM + ak;
        uint32_t adst = s2u(&As[0][am][ak]);
        bool isA = (tid >= 512);

        // prologue: stages 0,1
        #pragma unroll
        for (int st = 0; st < 2; st++) {
            int k0 = st * 16;
            cpa16(bdst1 + st*12800u, bsrc1 + (size_t)k0 * 1024);
            if (isA) cpa16(adst + st*5120u, asrc + k0);
            asm volatile("cp.async.commit_group;");
        }

        #pragma unroll 1
        for (int it = 0; it < 32; it++) {
            if (it == 31) asm volatile("cp.async.wait_group 0;");
            else          asm volatile("cp.async.wait_group 1;");
            __syncthreads();
            if (it < 30) {
                int st = (it + 2) % 3;
                int k0 = (it + 2) * 16;
                cpa16(bdst1 + st*12800u, bsrc1 + (size_t)k0 * 1024);
                if (isA) cpa16(adst + st*5120u, asrc + k0);
                asm volatile("cp.async.commit_group;");
            }
            if (computer) {
                int st = it % 3;
                #pragma unroll
                for (int ks = 0; ks < 16; ks += 8) {
                    uint32_t a[2][4], b[3][2];
                    #pragma unroll
                    for (int mt = 0; mt < 2; mt++) {
                        int mr = wm*32 + mt*16 + grp;
                        a[mt][0] = __float_as_uint(As[st][mr    ][ks + tid4]);
                        a[mt][1] = __float_as_uint(As[st][mr + 8][ks + tid4]);
                        a[mt][2] = __float_as_uint(As[st][mr    ][ks + tid4 + 4]);
                        a[mt][3] = __float_as_uint(As[st][mr + 8][ks + tid4 + 4]);
                    }
                    #pragma unroll
                    for (int nt = 0; nt < 3; nt++) {
                        int nc = wn*24 + nt*8 + grp;
                        b[nt][0] = __float_as_uint(Bs[st][ks + tid4    ][nc]);
                        b[nt][1] = __float_as_uint(Bs[st][ks + tid4 + 4][nc]);
                    }
                    #pragma unroll
                    for (int mt = 0; mt < 2; mt++)
                        #pragma unroll
                        for (int nt = 0; nt < 3; nt++) {
                            asm volatile(
                                "mma.sync.aligned.m16n8k8.row.col.f32.tf32.tf32.f32 "
                                "{%0,%1,%2,%3}, {%4,%5,%6,%7}, {%8,%9}, {%0,%1,%2,%3};"
                                : "+f"(c[mt][nt][0]), "+f"(c[mt][nt][1]),
                                  "+f"(c[mt][nt][2]), "+f"(c[mt][nt][3])
                                : "r"(a[mt][0]), "r"(a[mt][1]), "r"(a[mt][2]), "r"(a[mt][3]),
                                  "r"(b[nt][0]), "r"(b[nt][1]));
                        }
                }
            }
        }
        // store C
        if (computer) {
            #pragma unroll
            for (int mt = 0; mt < 2; mt++) {
                int r0 = m0 + wm*32 + mt*16 + grp;
                int r1 = r0 + 8;
                #pragma unroll
                for (int nt = 0; nt < 3; nt++) {
                    int col = n0 + wn*24 + nt*8 + 2*tid4;
                    if (r0 < M_ALL) {
                        G[(size_t)r0*GCOLS + col]     = c[mt][nt][0];
                        G[(size_t)r0*GCOLS + col + 1] = c[mt][nt][1];
                    }
                    if (r1 < M_ALL) {
                        G[(size_t)r1*GCOLS + col]     = c[mt][nt][2];
                        G[(size_t)r1*GCOLS + col + 1] = c[mt][nt][3];
                    }
                }
            }
        }
    } else {
        // -------------------- mining (task = bid - 112), 768 thr ------------
        __shared__ float invn[NEMB], sqv[NEMB];
        __shared__ float D[NEMB][NEMB];
        __shared__ int wcnt[24];
        __shared__ int base_sh;
        int k = bid - 112;
        int wid = tid >> 5, lane = tid & 31;

        const float4* xb4 = reinterpret_cast<const float4*>(X + (size_t)k * NEMB * DIM);
        float4* xs4 = reinterpret_cast<float4*>(xs);
        for (int i = tid; i < NEMB * (DIM/4); i += NTHR) xs4[i] = xb4[i];
        __syncthreads();

        for (int r = wid; r < NEMB; r += 24) {
            float s = 0.f;
            for (int d = lane; d < DIM; d += 32) { float v = xs[r*DIM + d]; s += v*v; }
            s = warp_sum(s);
            if (lane == 0) invn[r] = rsqrtf(s);
        }
        __syncthreads();
        for (int i = tid; i < NEMB*DIM; i += NTHR) xs[i] *= invn[i >> 9];
        __syncthreads();
        for (int r = wid; r < NEMB; r += 24) {
            float s = 0.f;
            for (int d = lane; d < DIM; d += 32) { float v = xs[r*DIM + d]; s += v*v; }
            s = warp_sum(s);
            if (lane == 0) sqv[r] = s;
        }
        __syncthreads();
        for (int p = wid; p < 300; p += 24) {
            int i = 0, rem = p;
            while (rem >= 24 - i) { rem -= 24 - i; i++; }
            int j = i + 1 + rem;
            float s = 0.f;
            for (int cc = lane; cc < DIM/4; cc += 32) {
                float4 a = xs4[i*(DIM/4) + cc];
                float4 b = xs4[j*(DIM/4) + cc];
                s += a.x*b.x + a.y*b.y + a.z*b.z + a.w*b.w;
            }
            s = warp_sum(s);
            if (lane == 0) {
                float d2 = sqv[i] + sqv[j] - 2.f*s;
                float dd = sqrtf(fmaxf(d2, 0.f));
                D[i][j] = dd; D[j][i] = dd;
            }
        }
        __syncthreads();

        if (tid == 0) base_sh = 0;
        __syncthreads();
        for (int rnd = 0; rnd < 3; rnd++) {
            int t = rnd*NTHR + tid;
            bool f = false; unsigned pack = 0;
            if (t < NTRIP) {
                int a  = t / 80;
                int rm = t - a*80;
                int pi = rm / 20, ni = rm - (rm/20)*20;
                int lbl = a % 5, ga = a / 5;
                int pg = pi + (pi >= ga ? 1 : 0);
                int p  = lbl + 5*pg;
                int m  = ni >> 2, w2 = ni & 3;
                int wn2 = w2 + (w2 >= lbl ? 1 : 0);
                int n  = 5*m + wn2;
                float tm = D[a][n] - D[a][p];
                f = (tm > 0.f && tm <= 0.8f);
                pack = (unsigned)(a | (p << 5) | (n << 10));
            }
            unsigned bal = __ballot_sync(0xffffffffu, f);
            if (lane == 0) wcnt[wid] = __popc(bal);
            __syncthreads();
            int off = base_sh;
            #pragma unroll
            for (int w24 = 0; w24 < 24; w24++) if (w24 < wid) off += wcnt[w24];
            off += __popc(bal & ((1u << lane) - 1u));
            if (f) trip[k*NTRIP + off] = pack;
            __syncthreads();
            if (tid == 0) {
                int s = 0;
                #pragma unroll
                for (int w24 = 0; w24 < 24; w24++) s += wcnt[w24];
                base_sh += s;
            }
            __syncthreads();
        }
        if (tid == 0) cnt[k] = base_sh;
    }
    grid_barrier(0, nb);

    // ============================ pool ============================
    float w2v[8];
    head_prefetch(W2, DIM, bid & 7, bid >> 3, tid, w2v);
    {
        int cb = bid & 7, k = bid >> 3;
        int w = tid >> 5, lane = tid & 31;
        const float* Gt = G + (size_t)k * NEMB * GCOLS;
        int n = cnt[k];
        for (int idx = tid; idx < 75*32; idx += NTHR) {
            int c = idx & 31, row = idx >> 5;
            int s = row / NEMB, i = row - s*NEMB;
            sG[row][c] = *reinterpret_cast<const float4*>(
                &Gt[(size_t)i*GCOLS + (s << 10) + (cb << 7) + (c << 2)]);
        }
        const unsigned* tp = trip + k*NTRIP;
        for (int i = tid; i < n; i += NTHR) strip[i] = __ldg(&tp[i]);
        __syncthreads();
        float4 b1v = *reinterpret_cast<const float4*>(&b1[(cb << 7) + (lane << 2)]);
        int lo = (w * n) / 24;
        int hi = ((w + 1) * n) / 24;
        float4 acc0 = make_float4(0.f, 0.f, 0.f, 0.f);
        float4 acc1 = make_float4(0.f, 0.f, 0.f, 0.f);
        int cur_a = -1, cur_p = -1;
        float4 fa = acc0, fap = acc0;
        int t = lo;
        for (; t + 1 < hi; t += 2) {
            unsigned u0 = strip[t], u1 = strip[t+1];
            int a0 = u0 & 31, p0 = (u0 >> 5) & 31, n0 = (u0 >> 10) & 31;
            int a1 = u1 & 31, p1 = (u1 >> 5) & 31, n1 = (u1 >> 10) & 31;
            if (a0 != cur_a) {
                float4 g = sG[a0][lane];
                fa.x = g.x + b1v.x; fa.y = g.y + b1v.y;
                fa.z = g.z + b1v.z; fa.w = g.w + b1v.w;
                cur_a = a0; cur_p = -1;
            }
            if (p0 != cur_p) {
                float4 g = sG[25 + p0][lane];
                fap.x = fa.x + g.x; fap.y = fa.y + g.y;
                fap.z = fa.z + g.z; fap.w = fa.w + g.w;
                cur_p = p0;
            }
            float4 gn0 = sG[50 + n0][lane];
            float4 fap0 = fap;
            if (a1 != cur_a) {
                float4 g = sG[a1][lane];
                fa.x = g.x + b1v.x; fa.y = g.y + b1v.y;
                fa.z = g.z + b1v.z; fa.w = g.w + b1v.w;
                cur_a = a1; cur_p = -1;
            }
            if (p1 != cur_p) {
                float4 g = sG[25 + p1][lane];
                fap.x = fa.x + g.x; fap.y = fa.y + g.y;
                fap.z = fa.z + g.z; fap.w = fa.w + g.w;
                cur_p = p1;
            }
            float4 gn1 = sG[50 + n1][lane];
            acc0.x += fmaxf(fap0.x + gn0.x, 0.f);
            acc0.y += fmaxf(fap0.y + gn0.y, 0.f);
            acc0.z += fmaxf(fap0.z + gn0.z, 0.f);
            acc0.w += fmaxf(fap0.w + gn0.w, 0.f);
            acc1.x += fmaxf(fap.x + gn1.x, 0.f);
            acc1.y += fmaxf(fap.y + gn1.y, 0.f);
            acc1.z += fmaxf(fap.z + gn1.z, 0.f);
            acc1.w += fmaxf(fap.w + gn1.w, 0.f);
        }
        if (t < hi) {
            unsigned u = strip[t];
            int a = u & 31, p = (u >> 5) & 31, nn = (u >> 10) & 31;
            if (a != cur_a) {
                float4 g = sG[a][lane];
                fa.x = g.x + b1v.x; fa.y = g.y + b1v.y;
                fa.z = g.z + b1v.z; fa.w = g.w + b1v.w;
                cur_a = a; cur_p = -1;
            }
            if (p != cur_p) {
                float4 g = sG[25 + p][lane];
                fap.x = fa.x + g.x; fap.y = fa.y + g.y;
                fap.z = fa.z + g.z; fap.w = fa.w + g.w;
                cur_p = p;
            }
            float4 gn = sG[50 + nn][lane];
            acc0.x += fmaxf(fap.x + gn.x, 0.f);
            acc0.y += fmaxf(fap.y + gn.y, 0.f);
            acc0.z += fmaxf(fap.z + gn.z, 0.f);
            acc0.w += fmaxf(fap.w + gn.w, 0.f);
        }
        acc0.x += acc1.x; acc0.y += acc1.y; acc0.z += acc1.z; acc0.w += acc1.w;
        red[w][lane] = acc0;
        __syncthreads();
        if (tid < 32) {
            float4 s = red[0][tid];
            #pragma unroll
            for (int g = 1; g < 24; g++) {
                float4 r = red[g][tid];
                s.x += r.x; s.y += r.y; s.z += r.z; s.w += r.w;
            }
            *reinterpret_cast<float4*>(&q[k*HID + (cb << 7) + (tid << 2)]) = s;
        }
    }
    grid_barrier(1, nb);

    head_compute(q, nullptr, nullptr, pooled, HID, DIM, 0, bid & 7, bid >> 3, sf, tid, w2v);
    float w3v[8];
    head_prefetch(W3, HID, bid & 15, bid >> 4, tid, w3v);
    grid_barrier(2, nb);

    head_compute(pooled, b2, cnt, t1, DIM, HID, 1, bid & 15, bid >> 4, sf, tid, w3v);
    float w4v[8];
    head_prefetch(W4, DIM, bid & 7, bid >> 3, tid, w4v);
    grid_barrier(3, nb);

    head_compute(t1, b3, nullptr, t2, HID, DIM, 2, bid & 7, bid >> 3, sf, tid, w4v);
    grid_barrier(4, nb);

    if (bid < NTASK && tid < 512) {
        int k = bid;
        int c = tid & 63, seg = tid >> 6;
        float acc = 0.f;
        const float* tk = t2 + k*DIM;
        for (int i = seg*64; i < seg*64 + 64; i++)
            acc += (tk[i] + b4v[i]) * Wc[i*NCPT + c];
        fred[seg][c] = acc;
        __syncwarp();
        asm volatile("bar.sync 3, 512;" ::: "memory");
        if (tid < NCPT) {
            float s = bc[c];
            #pragma unroll
            for (int g = 0; g < 8; g++) s += fred[g][c];
            sc[c] = s;
        }
        asm volatile("bar.sync 3, 512;" ::: "memory");
        if (tid < NCPT) {
            float v = sc[c];
            float mx = -1e30f;
            #pragma unroll
            for (int i = 0; i < NCPT; i++) mx = fmaxf(mx, sc[i]);
            float sum = 0.f;
            #pragma unroll
            for (int i = 0; i < NCPT; i++) sum += expf(sc[i] - mx);
            out[k*NCPT + c] = expf(v - mx) / sum;
        }
    }
}

// ---------------- launch ----------------
extern "C" void kernel_launch(void* const* d_in, const int* in_sizes, int n_in,
                              void* d_out, int out_size) {
    const float* X  = (const float*)d_in[0];
    const float* W1 = (const float*)d_in[1];
    const float* b1 = (const float*)d_in[2];
    const float* W2 = (const float*)d_in[3];
    const float* b2 = (const float*)d_in[4];
    const float* W3 = (const float*)d_in[5];
    const float* b3 = (const float*)d_in[6];
    const float* W4 = (const float*)d_in[7];
    const float* b4 = (const float*)d_in[8];
    const float* Wc = (const float*)d_in[9];
    const float* bc = (const float*)d_in[10];
    float* out = (float*)d_out;

    float *G, *q, *pooled, *t1, *t2; unsigned* trip; int* cnt;
    cudaGetSymbolAddress((void**)&G,      g_G);
    cudaGetSymbolAddress((void**)&trip,   g_trip);
    cudaGetSymbolAddress((void**)&cnt,    g_cnt);
    cudaGetSymbolAddress((void**)&q,      g_q);
    cudaGetSymbolAddress((void**)&pooled, g_pooled);
    cudaGetSymbolAddress((void**)&t1,     g_t1);
    cudaGetSymbolAddress((void**)&t2,     g_t2);

    // dynamic smem = max(mining 51.2KB, pool 38400+12288+8000 = 58.7KB)
    const int dsm = 75*32*16 + 24*32*16 + NTRIP*4;
    static int configured = 0;
    if (!configured) {
        cudaFuncSetAttribute(omega_kernel, cudaFuncAttributeMaxDynamicSharedMemorySize, dsm);
        configured = 1;
    }

    omega_kernel<<<NBLK, NTHR, dsm>>>(X, W1, b1, W2, b2, W3, b3, W4, b4, Wc, bc,
                                      G, trip, cnt, q, pooled, t1, t2, out);
}

// round 16
// speedup vs baseline: 1.0708x; 1.0708x over previous
#include <cuda_runtime.h>
#include <math.h>
#include <stdint.h>

#define NTASK 16
#define NEMB  25
#define DIM   512
#define HID   1024
#define NTRIP 2000
#define NCPT  64
#define M_ALL (NTASK*NEMB)   // 400
#define GCOLS (3*HID)        // 3072
#define NBLK  128            // one wave -> grid barrier safe

// ---------------- scratch ----------------
__device__ float    g_G[M_ALL*GCOLS];
__device__ unsigned g_trip[NTASK*NTRIP];
__device__ int      g_cnt[NTASK];
__device__ float    g_q[NTASK*HID];
__device__ float    g_pooled[NTASK*DIM];
__device__ float    g_t1[NTASK*HID];
__device__ float    g_t2[NTASK*DIM];
__device__ unsigned g_bcnt[5];
__device__ unsigned g_bgen[5];
// fine-grained dataflow counters (monotonic across runs; generation-checked)
__device__ unsigned g_ready[7];      // per 64-row m-group: +16 per run
__device__ unsigned g_cntrdy[16];    // per task: +1 per run
__device__ unsigned g_done;          // head3 completion: +128 per run

__device__ __forceinline__ float warp_sum(float v) {
    #pragma unroll
    for (int o = 16; o > 0; o >>= 1) v += __shfl_xor_sync(0xffffffffu, v, o);
    return v;
}

__device__ __forceinline__ uint32_t s2u(const void* p) {
    return (uint32_t)__cvta_generic_to_shared(p);
}

__device__ __forceinline__ void cpa16(uint32_t dst, const float* src) {
    asm volatile("cp.async.ca.shared.global [%0], [%1], 16;" :: "r"(dst), "l"(src));
}

__device__ __forceinline__ void grid_barrier(int s, unsigned nb) {
    __syncthreads();
    if (threadIdx.x == 0) {
        unsigned g0 = *((volatile unsigned*)&g_bgen[s]);
        __threadfence();
        unsigned old = atomicAdd(&g_bcnt[s], 1u);
        if (old == nb - 1u) {
            g_bcnt[s] = 0u;
            __threadfence();
            atomicAdd(&g_bgen[s], 1u);
        } else {
            while (*((volatile unsigned*)&g_bgen[s]) == g0) { }
            __threadfence();
        }
    }
    __syncthreads();
}

__device__ __forceinline__ void head_prefetch(const float* __restrict__ W,
                                              int Nout, int jb, int kb, int tid,
                                              float* wv) {
    int j  = jb*64 + (tid & 63);
    int kh = tid >> 6;
    #pragma unroll
    for (int ii = 0; ii < 8; ii++)
        wv[ii] = __ldg(&W[(size_t)(kb*64 + kh*8 + ii)*Nout + j]);
}

__device__ __forceinline__ void head_compute(const float* __restrict__ in,
                                             const float* __restrict__ bvec,
                                             const int* __restrict__ cntp,
                                             float* __restrict__ outp,
                                             int Nin, int Nout, int mode,
                                             int jb, int kb,
                                             float (*sf)[16], int tid,
                                             const float* wv) {
    int kb64 = kb * 64;
    for (int idx = tid; idx < 1024; idx += 512) {
        int il = idx >> 4, t = idx & 15;
        float v = in[t*Nin + kb64 + il];
        if (mode == 1)      v += (float)cntp[t] * bvec[kb64 + il];
        else if (mode == 2) v  = fmaxf(v + bvec[kb64 + il], 0.f);
        sf[il][t] = v;
    }
    __syncthreads();
    int j  = jb*64 + (tid & 63);
    int kh = tid >> 6;
    float acc[16];
    #pragma unroll
    for (int t = 0; t < 16; t++) acc[t] = 0.f;
    const float4* sf4 = reinterpret_cast<const float4*>(sf);
    #pragma unroll
    for (int ii = 0; ii < 8; ii++) {
        int i = (kh << 3) + ii;
        float w = wv[ii];
        float4 f0 = sf4[i*4 + 0];
        float4 f1 = sf4[i*4 + 1];
        float4 f2 = sf4[i*4 + 2];
        float4 f3 = sf4[i*4 + 3];
        acc[0]  += f0.x*w; acc[1]  += f0.y*w; acc[2]  += f0.z*w; acc[3]  += f0.w*w;
        acc[4]  += f1.x*w; acc[5]  += f1.y*w; acc[6]  += f1.z*w; acc[7]  += f1.w*w;
        acc[8]  += f2.x*w; acc[9]  += f2.y*w; acc[10] += f2.z*w; acc[11] += f2.w*w;
        acc[12] += f3.x*w; acc[13] += f3.y*w; acc[14] += f3.z*w; acc[15] += f3.w*w;
    }
    #pragma unroll
    for (int t = 0; t < 16; t++)
        atomicAdd(&outp[t*Nout + j], acc[t]);
}

// ============================================================================
// ONE persistent kernel: [gemm | mining] ~dataflow~> pool -> h1 -> h2 -> h3
//                        ~counter~> final (blocks 0..15; rest exit)
// ============================================================================
__global__ __launch_bounds__(512) void omega_kernel(const float* __restrict__ X,
                                                    const float* __restrict__ W1,
                                                    const float* __restrict__ b1,
                                                    const float* __restrict__ W2,
                                                    const float* __restrict__ b2,
                                                    const float* __restrict__ W3,
                                                    const float* __restrict__ b3,
                                                    const float* __restrict__ W4,
                                                    const float* __restrict__ b4v,
                                                    const float* __restrict__ Wc,
                                                    const float* __restrict__ bc,
                                                    float* __restrict__ G,
                                                    unsigned* __restrict__ trip,
                                                    int* __restrict__ cnt,
                                                    float* __restrict__ q,
                                                    float* __restrict__ pooled,
                                                    float* __restrict__ t1,
                                                    float* __restrict__ t2,
                                                    float* __restrict__ out) {
    extern __shared__ char dsm[];
    float*    xs   = reinterpret_cast<float*>(dsm);                      // mining
    float4 (*sG)[32]   = reinterpret_cast<float4(*)[32]>(dsm);          // pool
    char* rbm = dsm + 75*32*16;
    float4 (*red)[32]  = reinterpret_cast<float4(*)[32]>(rbm);
    float  (*sf)[16]   = reinterpret_cast<float(*)[16]>(rbm);
    float  (*fred)[64] = reinterpret_cast<float(*)[64]>(rbm);
    float*  sc         = reinterpret_cast<float*>(rbm + 8*64*4);
    unsigned* strip    = reinterpret_cast<unsigned*>(rbm + 8192);

    __shared__ unsigned sR;      // completed-run count snapshot
    // GEMM pipeline buffers (3-stage cp.async), conflict-free padded
    __shared__ __align__(16) float As[3][64][20];    // 15360 B
    __shared__ __align__(16) float Bs[3][16][200];   // 38400 B

    int bid = blockIdx.x;
    int tid = threadIdx.x;
    unsigned nb = gridDim.x;

    if (tid == 0) sR = *((volatile unsigned*)&g_bgen[1]);
    // ---- zero atomic accumulators ----
    {
        int gidx = bid*512 + tid;
        if (gidx < NTASK*DIM)  pooled[gidx] = 0.f;
        if (gidx < NTASK*HID)  t1[gidx]     = 0.f;
        if (gidx < NTASK*DIM)  t2[gidx]     = 0.f;
    }
    __syncthreads();
    unsigned R = sR;

    // ============================ stage A ============================
    if (bid < 112) {
        // -------- GEMM: BM=64, BN=192, BK=16, warps 0-7 compute (tile 32x48) --
        int m0 = (bid >> 4) * 64;
        int n0 = (bid & 15) * 192;
        int w = tid >> 5, lane = tid & 31;
        int wm = w & 1, wn = w >> 1;
        int grp = lane >> 2, tid4 = lane & 3;
        bool computer = (w < 8);

        float c[2][6][4];
        #pragma unroll
        for (int mt = 0; mt < 2; mt++)
            #pragma unroll
            for (int nt = 0; nt < 6; nt++)
                #pragma unroll
                for (int r = 0; r < 4; r++) c[mt][nt][r] = 0.f;

        // ---- loader precompute ----
        int brow1 = tid / 48, bcol1 = (tid - brow1*48) * 4;
        int gc1 = n0 + bcol1;
        const float* bsrc1 = W1 + ((size_t)(((gc1 >> 10) << 9)) + brow1) * 1024 + (gc1 & 1023);
        uint32_t bdst1 = s2u(&Bs[0][brow1][bcol1]);

        int c2i = tid + 512;
        int brow2 = c2i / 48, bcol2 = (c2i - brow2*48) * 4;
        int gc2 = n0 + bcol2;
        const float* bsrc2 = W1 + ((size_t)(((gc2 >> 10) << 9)) + brow2) * 1024 + (gc2 & 1023);
        uint32_t bdst2 = s2u(&Bs[0][brow2 & 15][bcol2]);

        int ac = tid - 256;
        int am = (ac >> 2) & 63, ak = (ac & 3) << 2;
        int gm = m0 + am; if (gm >= M_ALL) gm = M_ALL - 1;
        const float* asrc = X + (size_t)gm * DIM + ak;
        uint32_t adst = s2u(&As[0][am][ak]);
        bool isA = (tid >= 256);

        // prologue: stages 0,1
        #pragma unroll
        for (int st = 0; st < 2; st++) {
            int k0 = st * 16;
            cpa16(bdst1 + st*12800u, bsrc1 + (size_t)k0 * 1024);
            if (!isA) cpa16(bdst2 + st*12800u, bsrc2 + (size_t)k0 * 1024);
            else      cpa16(adst  + st*5120u,  asrc + k0);
            asm volatile("cp.async.commit_group;");
        }

        #pragma unroll 1
        for (int it = 0; it < 32; it++) {
            if (it == 31) asm volatile("cp.async.wait_group 0;");
            else          asm volatile("cp.async.wait_group 1;");
            __syncthreads();
            if (it < 30) {
                int st = (it + 2) % 3;
                int k0 = (it + 2) * 16;
                cpa16(bdst1 + st*12800u, bsrc1 + (size_t)k0 * 1024);
                if (!isA) cpa16(bdst2 + st*12800u, bsrc2 + (size_t)k0 * 1024);
                else      cpa16(adst  + st*5120u,  asrc + k0);
                asm volatile("cp.async.commit_group;");
            }
            if (computer) {
                int st = it % 3;
                #pragma unroll
                for (int ks = 0; ks < 16; ks += 8) {
                    uint32_t a[2][4], b[6][2];
                    #pragma unroll
                    for (int mt = 0; mt < 2; mt++) {
                        int mr = wm*32 + mt*16 + grp;
                        a[mt][0] = __float_as_uint(As[st][mr    ][ks + tid4]);
                        a[mt][1] = __float_as_uint(As[st][mr + 8][ks + tid4]);
                        a[mt][2] = __float_as_uint(As[st][mr    ][ks + tid4 + 4]);
                        a[mt][3] = __float_as_uint(As[st][mr + 8][ks + tid4 + 4]);
                    }
                    #pragma unroll
                    for (int nt = 0; nt < 6; nt++) {
                        int nc = wn*48 + nt*8 + grp;
                        b[nt][0] = __float_as_uint(Bs[st][ks + tid4    ][nc]);
                        b[nt][1] = __float_as_uint(Bs[st][ks + tid4 + 4][nc]);
                    }
                    #pragma unroll
                    for (int mt = 0; mt < 2; mt++)
                        #pragma unroll
                        for (int nt = 0; nt < 6; nt++) {
                            asm volatile(
                                "mma.sync.aligned.m16n8k8.row.col.f32.tf32.tf32.f32 "
                                "{%0,%1,%2,%3}, {%4,%5,%6,%7}, {%8,%9}, {%0,%1,%2,%3};"
                                : "+f"(c[mt][nt][0]), "+f"(c[mt][nt][1]),
                                  "+f"(c[mt][nt][2]), "+f"(c[mt][nt][3])
                                : "r"(a[mt][0]), "r"(a[mt][1]), "r"(a[mt][2]), "r"(a[mt][3]),
                                  "r"(b[nt][0]), "r"(b[nt][1]));
                        }
                }
            }
        }
        // store C
        if (computer) {
            #pragma unroll
            for (int mt = 0; mt < 2; mt++) {
                int r0 = m0 + wm*32 + mt*16 + grp;
                int r1 = r0 + 8;
                #pragma unroll
                for (int nt = 0; nt < 6; nt++) {
                    int col = n0 + wn*48 + nt*8 + 2*tid4;
                    if (r0 < M_ALL) {
                        G[(size_t)r0*GCOLS + col]     = c[mt][nt][0];
                        G[(size_t)r0*GCOLS + col + 1] = c[mt][nt][1];
                    }
                    if (r1 < M_ALL) {
                        G[(size_t)r1*GCOLS + col]     = c[mt][nt][2];
                        G[(size_t)r1*GCOLS + col + 1] = c[mt][nt][3];
                    }
                }
            }
        }
        // signal this m-group n-chunk done
        __syncthreads();
        if (tid == 0) {
            __threadfence();
            atomicAdd(&g_ready[bid >> 4], 1u);
        }
    } else {
        // -------------------- mining (task = bid - 112), 512 thr ------------
        __shared__ float invn[NEMB], sqv[NEMB];
        __shared__ float D[NEMB][NEMB];
        __shared__ int wcnt[16];
        __shared__ int base_sh;
        int k = bid - 112;
        int wid = tid >> 5, lane = tid & 31;

        const float4* xb4 = reinterpret_cast<const float4*>(X + (size_t)k * NEMB * DIM);
        float4* xs4 = reinterpret_cast<float4*>(xs);
        for (int i = tid; i < NEMB * (DIM/4); i += 512) xs4[i] = xb4[i];
        __syncthreads();

        for (int r = wid; r < NEMB; r += 16) {
            float s = 0.f;
            for (int d = lane; d < DIM; d += 32) { float v = xs[r*DIM + d]; s += v*v; }
            s = warp_sum(s);
            if (lane == 0) invn[r] = rsqrtf(s);
        }
        __syncthreads();
        for (int i = tid; i < NEMB*DIM; i += 512) xs[i] *= invn[i >> 9];
        __syncthreads();
        for (int r = wid; r < NEMB; r += 16) {
            float s = 0.f;
            for (int d = lane; d < DIM; d += 32) { float v = xs[r*DIM + d]; s += v*v; }
            s = warp_sum(s);
            if (lane == 0) sqv[r] = s;
        }
        __syncthreads();
        for (int p = wid; p < 300; p += 16) {
            int i = 0, rem = p;
            while (rem >= 24 - i) { rem -= 24 - i; i++; }
            int j = i + 1 + rem;
            float s = 0.f;
            for (int cc = lane; cc < DIM/4; cc += 32) {
                float4 a = xs4[i*(DIM/4) + cc];
                float4 b = xs4[j*(DIM/4) + cc];
                s += a.x*b.x + a.y*b.y + a.z*b.z + a.w*b.w;
            }
            s = warp_sum(s);
            if (lane == 0) {
                float d2 = sqv[i] + sqv[j] - 2.f*s;
                float dd = sqrtf(fmaxf(d2, 0.f));
                D[i][j] = dd; D[j][i] = dd;
            }
        }
        __syncthreads();

        if (tid == 0) base_sh = 0;
        __syncthreads();
        for (int rnd = 0; rnd < 4; rnd++) {
            int t = rnd*512 + tid;
            bool f = false; unsigned pack = 0;
            if (t < NTRIP) {
                int a  = t / 80;
                int rm = t - a*80;
                int pi = rm / 20, ni = rm - (rm/20)*20;
                int lbl = a % 5, ga = a / 5;
                int pg = pi + (pi >= ga ? 1 : 0);
                int p  = lbl + 5*pg;
                int m  = ni >> 2, w2 = ni & 3;
                int wn2 = w2 + (w2 >= lbl ? 1 : 0);
                int n  = 5*m + wn2;
                float tm = D[a][n] - D[a][p];
                f = (tm > 0.f && tm <= 0.8f);
                pack = (unsigned)(a | (p << 5) | (n << 10));
            }
            unsigned bal = __ballot_sync(0xffffffffu, f);
            if (lane == 0) wcnt[wid] = __popc(bal);
            __syncthreads();
            int off = base_sh;
            #pragma unroll
            for (int w16 = 0; w16 < 16; w16++) if (w16 < wid) off += wcnt[w16];
            off += __popc(bal & ((1u << lane) - 1u));
            if (f) trip[k*NTRIP + off] = pack;
            __syncthreads();
            if (tid == 0) {
                int s = 0;
                #pragma unroll
                for (int w16 = 0; w16 < 16; w16++) s += wcnt[w16];
                base_sh += s;
            }
            __syncthreads();
        }
        if (tid == 0) {
            cnt[k] = base_sh;
            __threadfence();
            atomicAdd(&g_cntrdy[k], 1u);
        }
    }

    // ============================ pool (dataflow wait) ============================
    float w2v[8];
    head_prefetch(W2, DIM, bid & 7, bid >> 3, tid, w2v);
    {
        int cb = bid & 7, k = bid >> 3;
        // wait for required G m-groups and this task's triplets
        if (tid == 0) {
            int mg0 = (25*k) >> 6;
            int mg1 = (25*k + 24) >> 6;
            unsigned gtgt = 16u * (R + 1u);
            while (*((volatile unsigned*)&g_ready[mg0]) < gtgt) { }
            if (mg1 != mg0)
                while (*((volatile unsigned*)&g_ready[mg1]) < gtgt) { }
            while (*((volatile unsigned*)&g_cntrdy[k]) < R + 1u) { }
            __threadfence();
        }
        __syncthreads();

        int w = tid >> 5, lane = tid & 31;
        const float* Gt = G + (size_t)k * NEMB * GCOLS;
        int n = cnt[k];
        for (int idx = tid; idx < 75*32; idx += 512) {
            int c = idx & 31, row = idx >> 5;
            int s = row / NEMB, i = row - s*NEMB;
            sG[row][c] = *reinterpret_cast<const float4*>(
                &Gt[(size_t)i*GCOLS + (s << 10) + (cb << 7) + (c << 2)]);
        }
        const unsigned* tp = trip + k*NTRIP;
        for (int i = tid; i < n; i += 512) strip[i] = __ldg(&tp[i]);
        __syncthreads();
        float4 b1v = *reinterpret_cast<const float4*>(&b1[(cb << 7) + (lane << 2)]);
        int lo = (w * n) >> 4;
        int hi = ((w + 1) * n) >> 4;
        float4 acc0 = make_float4(0.f, 0.f, 0.f, 0.f);
        float4 acc1 = make_float4(0.f, 0.f, 0.f, 0.f);
        int cur_a = -1, cur_p = -1;
        float4 fa = acc0, fap = acc0;
        int t = lo;
        for (; t + 1 < hi; t += 2) {
            unsigned u0 = strip[t], u1 = strip[t+1];
            int a0 = u0 & 31, p0 = (u0 >> 5) & 31, n0 = (u0 >> 10) & 31;
            int a1 = u1 & 31, p1 = (u1 >> 5) & 31, n1 = (u1 >> 10) & 31;
            if (a0 != cur_a) {
                float4 g = sG[a0][lane];
                fa.x = g.x + b1v.x; fa.y = g.y + b1v.y;
                fa.z = g.z + b1v.z; fa.w = g.w + b1v.w;
                cur_a = a0; cur_p = -1;
            }
            if (p0 != cur_p) {
                float4 g = sG[25 + p0][lane];
                fap.x = fa.x + g.x; fap.y = fa.y + g.y;
                fap.z = fa.z + g.z; fap.w = fa.w + g.w;
                cur_p = p0;
            }
            float4 gn0 = sG[50 + n0][lane];
            float4 fap0 = fap;
            if (a1 != cur_a) {
                float4 g = sG[a1][lane];
                fa.x = g.x + b1v.x; fa.y = g.y + b1v.y;
                fa.z = g.z + b1v.z; fa.w = g.w + b1v.w;
                cur_a = a1; cur_p = -1;
            }
            if (p1 != cur_p) {
                float4 g = sG[25 + p1][lane];
                fap.x = fa.x + g.x; fap.y = fa.y + g.y;
                fap.z = fa.z + g.z; fap.w = fa.w + g.w;
                cur_p = p1;
            }
            float4 gn1 = sG[50 + n1][lane];
            acc0.x += fmaxf(fap0.x + gn0.x, 0.f);
            acc0.y += fmaxf(fap0.y + gn0.y, 0.f);
            acc0.z += fmaxf(fap0.z + gn0.z, 0.f);
            acc0.w += fmaxf(fap0.w + gn0.w, 0.f);
            acc1.x += fmaxf(fap.x + gn1.x, 0.f);
            acc1.y += fmaxf(fap.y + gn1.y, 0.f);
            acc1.z += fmaxf(fap.z + gn1.z, 0.f);
            acc1.w += fmaxf(fap.w + gn1.w, 0.f);
        }
        if (t < hi) {
            unsigned u = strip[t];
            int a = u & 31, p = (u >> 5) & 31, nn = (u >> 10) & 31;
            if (a != cur_a) {
                float4 g = sG[a][lane];
                fa.x = g.x + b1v.x; fa.y = g.y + b1v.y;
                fa.z = g.z + b1v.z; fa.w = g.w + b1v.w;
                cur_a = a; cur_p = -1;
            }
            if (p != cur_p) {
                float4 g = sG[25 + p][lane];
                fap.x = fa.x + g.x; fap.y = fa.y + g.y;
                fap.z = fa.z + g.z; fap.w = fa.w + g.w;
                cur_p = p;
            }
            float4 gn = sG[50 + nn][lane];
            acc0.x += fmaxf(fap.x + gn.x, 0.f);
            acc0.y += fmaxf(fap.y + gn.y, 0.f);
            acc0.z += fmaxf(fap.z + gn.z, 0.f);
            acc0.w += fmaxf(fap.w + gn.w, 0.f);
        }
        acc0.x += acc1.x; acc0.y += acc1.y; acc0.z += acc1.z; acc0.w += acc1.w;
        red[w][lane] = acc0;
        __syncthreads();
        if (tid < 32) {
            float4 s = red[0][tid];
            #pragma unroll
            for (int g = 1; g < 16; g++) {
                float4 r = red[g][tid];
                s.x += r.x; s.y += r.y; s.z += r.z; s.w += r.w;
            }
            *reinterpret_cast<float4*>(&q[k*HID + (cb << 7) + (tid << 2)]) = s;
        }
    }
    grid_barrier(1, nb);

    head_compute(q, nullptr, nullptr, pooled, HID, DIM, 0, bid & 7, bid >> 3, sf, tid, w2v);
    float w3v[8];
    head_prefetch(W3, HID, bid & 15, bid >> 4, tid, w3v);
    grid_barrier(2, nb);

    head_compute(pooled, b2, cnt, t1, DIM, HID, 1, bid & 15, bid >> 4, sf, tid, w3v);
    float w4v[8];
    head_prefetch(W4, DIM, bid & 7, bid >> 3, tid, w4v);
    grid_barrier(3, nb);

    head_compute(t1, b3, nullptr, t2, HID, DIM, 2, bid & 7, bid >> 3, sf, tid, w4v);

    // signal head3 completion; non-finalist blocks exit
    __syncthreads();
    if (tid == 0) {
        __threadfence();
        atomicAdd(&g_done, 1u);
    }
    if (bid >= NTASK) return;

    // ============================ final (blocks 0..15) ============================
    if (tid == 0) {
        unsigned tgt = 128u * (R + 1u);
        while (*((volatile unsigned*)&g_done) < tgt) { }
        __threadfence();
    }
    __syncthreads();
    {
        int k = bid;
        int c = tid & 63, seg = tid >> 6;
        float acc = 0.f;
        const float* tk = t2 + k*DIM;
        for (int i = seg*64; i < seg*64 + 64; i++)
            acc += (tk[i] + b4v[i]) * Wc[i*NCPT + c];
        fred[seg][c] = acc;
        __syncthreads();
        if (tid < NCPT) {
            float s = bc[c];
            #pragma unroll
            for (int g = 0; g < 8; g++) s += fred[g][c];
            sc[c] = s;
        }
        __syncthreads();
        if (tid < NCPT) {
            float v = sc[c];
            float mx = -1e30f;
            #pragma unroll
            for (int i = 0; i < NCPT; i++) mx = fmaxf(mx, sc[i]);
            float sum = 0.f;
            #pragma unroll
            for (int i = 0; i < NCPT; i++) sum += expf(sc[i] - mx);
            out[k*NCPT + c] = expf(v - mx) / sum;
        }
    }
}

// ---------------- launch ----------------
extern "C" void kernel_launch(void* const* d_in, const int* in_sizes, int n_in,
                              void* d_out, int out_size) {
    const float* X  = (const float*)d_in[0];
    const float* W1 = (const float*)d_in[1];
    const float* b1 = (const float*)d_in[2];
    const float* W2 = (const float*)d_in[3];
    const float* b2 = (const float*)d_in[4];
    const float* W3 = (const float*)d_in[5];
    const float* b3 = (const float*)d_in[6];
    const float* W4 = (const float*)d_in[7];
    const float* b4 = (const float*)d_in[8];
    const float* Wc = (const float*)d_in[9];
    const float* bc = (const float*)d_in[10];
    float* out = (float*)d_out;

    float *G, *q, *pooled, *t1, *t2; unsigned* trip; int* cnt;
    cudaGetSymbolAddress((void**)&G,      g_G);
    cudaGetSymbolAddress((void**)&trip,   g_trip);
    cudaGetSymbolAddress((void**)&cnt,    g_cnt);
    cudaGetSymbolAddress((void**)&q,      g_q);
    cudaGetSymbolAddress((void**)&pooled, g_pooled);
    cudaGetSymbolAddress((void**)&t1,     g_t1);
    cudaGetSymbolAddress((void**)&t2,     g_t2);

    // dynamic smem = max(mining 51.2KB, pool 38400+8192+8000 = 54.6KB)
    const int dsm = 75*32*16 + 16*32*16 + NTRIP*4;
    static int configured = 0;
    if (!configured) {
        cudaFuncSetAttribute(omega_kernel, cudaFuncAttributeMaxDynamicSharedMemorySize, dsm);
        configured = 1;
    }

    omega_kernel<<<NBLK, 512, dsm>>>(X, W1, b1, W2, b2, W3, b3, W4, b4, Wc, bc,
                                     G, trip, cnt, q, pooled, t1, t2, out);
}